// round 15
// baseline (speedup 1.0000x reference)
#include <cuda_runtime.h>
#include <cstdint>

// PSRoIPool, fused single kernel, NO prefix scan:
//   (a) ballot-compact batch-b rois + decode this block's (i,j) bounds,
//   (b) stage plane (b,p) LDG.128 -> STS.128 (padded float4 layout),
//   (c) gather: per-roi masked float4 window sums from raw plane.
// x (4, 1029, 96, 96) fp32, rois (512,5) fp32, out (512, 21, 7, 7) fp32.
// Grid (1029, 4).
//
// NUMERIC CONTRACT (verified R5): bin sizes are reciprocal-multiplies
// __fmul_rn(extent, fl(1/7)) — NOT divisions. Do not change.

#define C_TOT   1029
#define PH      7
#define PW      7
#define HH      96
#define WW      96
#define W4      24            // float4s per row
#define WP4     25            // padded float4 row stride (100 floats)
#define PLANE   (HH*WW)
#define KROIS   512
#define NBATCH  4
#define SCALE   0.0625f
#define RCP7    0.1428571492433547973632812500f   // fl(1/7) = 0x3E124925
#define THREADS 256

__global__ __launch_bounds__(THREADS) void psroi_direct(
    const float* __restrict__ x,
    const float* __restrict__ rois,
    float* __restrict__ out)
{
    __shared__ float4   sp4[HH * WP4];     // 38400 B raw plane (padded)
    __shared__ int      s_kk [KROIS];      // compacted roi ids (batch b)
    __shared__ uint32_t s_bnd[KROIS];      // hs | he<<8 | ws<<16 | we<<24
    __shared__ int      s_cnt;

    const int p    = blockIdx.x;           // plane/channel 0..1028
    const int b    = blockIdx.y;           // batch 0..3
    const int ij   = p % (PH * PW);
    const int i    = ij / PW;
    const int j    = ij - i * PW;
    const int tid  = threadIdx.x;
    const int lane = tid & 31;

    if (tid == 0) s_cnt = 0;
    __syncthreads();

    // ---- (b) Stage plane (b,p): coalesced LDG.128 -> STS.128.
    const float4* __restrict__ src4 =
        (const float4*)(x + ((size_t)b * C_TOT + p) * PLANE);
    #pragma unroll
    for (int q = 0; q < PLANE / 4 / THREADS; ++q) {      // 9
        const int e   = tid + q * THREADS;
        const int row = e / W4;
        const int c4  = e - row * W4;
        sp4[row * WP4 + c4] = __ldg(src4 + e);
    }

    // ---- (a) Ballot-compact + decode rois of batch b (2 per thread).
    #pragma unroll
    for (int t = 0; t < 2; ++t) {
        const int k = tid + t * THREADS;
        const float* roi = rois + k * 5;
        const bool match = ((int)__ldg(roi) == b);
        const unsigned m = __ballot_sync(0xffffffffu, match);
        int base;
        if (lane == 0) base = atomicAdd(&s_cnt, __popc(m));
        base = __shfl_sync(0xffffffffu, base, 0);
        if (match) {
            const int sw = (int)floorf(__fmaf_rn(__ldg(roi + 1), SCALE, 0.5f));
            const int sh = (int)floorf(__fmaf_rn(__ldg(roi + 2), SCALE, 0.5f));
            const int ew = (int)floorf(__fmaf_rn(__ldg(roi + 3), SCALE, 0.5f));
            const int eh = (int)floorf(__fmaf_rn(__ldg(roi + 4), SCALE, 0.5f));
            const float bin_h = __fmul_rn((float)max(eh - sh, 1), RCP7);
            const float bin_w = __fmul_rn((float)max(ew - sw, 1), RCP7);
            const int hs = min(max((int)floorf(__fmul_rn((float)i,       bin_h)) + sh, 0), HH);
            const int he = min(max((int)ceilf (__fmul_rn((float)(i + 1), bin_h)) + sh, 0), HH);
            const int ws = min(max((int)floorf(__fmul_rn((float)j,       bin_w)) + sw, 0), WW);
            const int we = min(max((int)ceilf (__fmul_rn((float)(j + 1), bin_w)) + sw, 0), WW);
            const int pos = base + __popc(m & ((1u << lane) - 1u));
            s_kk [pos] = k;
            s_bnd[pos] = (uint32_t)hs | ((uint32_t)he << 8)
                       | ((uint32_t)ws << 16) | ((uint32_t)we << 24);
        }
    }
    __syncthreads();

    // ---- (c) Gather: masked float4 window sums (all active lanes busy).
    const int cnt = s_cnt;
    for (int n = tid; n < cnt; n += THREADS) {
        const uint32_t bnd = s_bnd[n];
        const int hs = bnd & 0xff;
        const int he = (bnd >> 8) & 0xff;
        const int ws = (bnd >> 16) & 0xff;
        const int we = bnd >> 24;
        const int kk = s_kk[n];

        const int area = (he - hs) * (we - ws);
        float val = 0.0f;
        if (area > 0) {
            const int q0 = ws >> 2;
            const int q1 = (we - 1) >> 2;
            float acc = 0.0f;
            for (int hy = hs; hy < he; ++hy) {
                const float4* __restrict__ rr = sp4 + hy * WP4;
                for (int q = q0; q <= q1; ++q) {
                    const float4 v = rr[q];
                    const int c0 = q << 2;
                    acc += (c0     >= ws && c0     < we) ? v.x : 0.0f;
                    acc += (c0 + 1 >= ws && c0 + 1 < we) ? v.y : 0.0f;
                    acc += (c0 + 2 >= ws && c0 + 2 < we) ? v.z : 0.0f;
                    acc += (c0 + 3 >= ws && c0 + 3 < we) ? v.w : 0.0f;
                }
            }
            val = __fdiv_rn(acc, (float)area);
        }
        out[kk * C_TOT + p] = val;
    }
}

extern "C" void kernel_launch(void* const* d_in, const int* in_sizes, int n_in,
                              void* d_out, int out_size)
{
    const float* x;
    const float* rois;
    if (n_in >= 2 && in_sizes[0] == KROIS * 5) {
        rois = (const float*)d_in[0];
        x    = (const float*)d_in[1];
    } else {
        x    = (const float*)d_in[0];
        rois = (const float*)d_in[1];
    }
    float* out = (float*)d_out;

    dim3 grid(C_TOT, NBATCH);
    psroi_direct<<<grid, THREADS>>>(x, rois, out);
}

// round 16
// speedup vs baseline: 1.9315x; 1.9315x over previous
#include <cuda_runtime.h>
#include <cstdint>

// PSRoIPool, fused multi-plane kernel.
// x (4, 1029, 96, 96) fp32, rois (512,5) fp32, out (512, 21, 7, 7) fp32.
// Grid (49, 3, 4): block = (ij, c_group, b). All planes p = c*49+ij share
// (i,j) -> decode roi bounds ONCE (ballot-compacted into smem), then loop
// over 7 planes: stage (LDG.128->STS.128) -> float4 row-prefix scan ->
// prefix-difference gather.
//
// NUMERIC CONTRACT (verified R5): bin sizes are reciprocal-multiplies
// __fmul_rn(extent, fl(1/7)) — NOT divisions. Do not change.

#define C_TOT   1029
#define C_OUT   21
#define PH      7
#define PW      7
#define HH      96
#define WW      96
#define W4      24            // float4s per row
#define WP4     25            // padded float4 row stride (100 floats)
#define WPF     (WP4*4)
#define PLANE   (HH*WW)
#define KROIS   512
#define NBATCH  4
#define SCALE   0.0625f
#define RCP7    0.1428571492433547973632812500f   // fl(1/7) = 0x3E124925
#define THREADS 256
#define CGRP    7             // planes per block (21 = 3 groups of 7)

__global__ __launch_bounds__(THREADS) void psroi_fused7(
    const float* __restrict__ x,
    const float* __restrict__ rois,
    float* __restrict__ out)
{
    __shared__ float4   sp4[HH * WP4];     // 38400 B plane / prefix buffer
    __shared__ int      s_kk [KROIS];      // compacted roi ids (batch b)
    __shared__ uint32_t s_bnd[KROIS];      // hs | he<<8 | ws<<16 | we<<24
    __shared__ int      s_cnt;
    float* const sp = (float*)sp4;

    const int ijx  = blockIdx.x;           // 0..48
    const int cg   = blockIdx.y;           // 0..2
    const int b    = blockIdx.z;           // 0..3
    const int i    = ijx / PW;
    const int j    = ijx - i * PW;
    const int tid  = threadIdx.x;
    const int lane = tid & 31;

    if (tid == 0) s_cnt = 0;
    __syncthreads();

    // ---- Decode + ballot-compact rois of batch b (once per block).
    #pragma unroll
    for (int t = 0; t < 2; ++t) {
        const int k = tid + t * THREADS;
        const float* roi = rois + k * 5;
        const bool match = ((int)__ldg(roi) == b);
        const unsigned m = __ballot_sync(0xffffffffu, match);
        int base;
        if (lane == 0) base = atomicAdd(&s_cnt, __popc(m));
        base = __shfl_sync(0xffffffffu, base, 0);
        if (match) {
            const int sw = (int)floorf(__fmaf_rn(__ldg(roi + 1), SCALE, 0.5f));
            const int sh = (int)floorf(__fmaf_rn(__ldg(roi + 2), SCALE, 0.5f));
            const int ew = (int)floorf(__fmaf_rn(__ldg(roi + 3), SCALE, 0.5f));
            const int eh = (int)floorf(__fmaf_rn(__ldg(roi + 4), SCALE, 0.5f));
            const float bin_h = __fmul_rn((float)max(eh - sh, 1), RCP7);
            const float bin_w = __fmul_rn((float)max(ew - sw, 1), RCP7);
            const int hs = min(max((int)floorf(__fmul_rn((float)i,       bin_h)) + sh, 0), HH);
            const int he = min(max((int)ceilf (__fmul_rn((float)(i + 1), bin_h)) + sh, 0), HH);
            const int ws = min(max((int)floorf(__fmul_rn((float)j,       bin_w)) + sw, 0), WW);
            const int we = min(max((int)ceilf (__fmul_rn((float)(j + 1), bin_w)) + sw, 0), WW);
            const int pos = base + __popc(m & ((1u << lane) - 1u));
            s_kk [pos] = k;
            s_bnd[pos] = (uint32_t)hs | ((uint32_t)he << 8)
                       | ((uint32_t)ws << 16) | ((uint32_t)we << 24);
        }
    }
    __syncthreads();
    const int cnt = s_cnt;

    // ---- Loop over this block's 7 planes.
    for (int c = cg * CGRP; c < cg * CGRP + CGRP; ++c) {
        const int p = c * (PH * PW) + ijx;

        // Stage plane (b,p): coalesced LDG.128 -> STS.128 (padded layout).
        const float4* __restrict__ src4 =
            (const float4*)(x + ((size_t)b * C_TOT + p) * PLANE);
        #pragma unroll
        for (int q = 0; q < PLANE / 4 / THREADS; ++q) {      // 9
            const int e   = tid + q * THREADS;
            const int row = e / W4;
            const int c4  = e - row * W4;
            sp4[row * WP4 + c4] = __ldg(src4 + e);
        }
        __syncthreads();

        // Row prefix (float4 pipeline, short carry chain).
        if (tid < HH) {
            float4* __restrict__ rr = sp4 + tid * WP4;
            float run = 0.0f;
            #pragma unroll
            for (int q = 0; q < W4; ++q) {
                float4 v = rr[q];
                const float s01 = v.x + v.y;
                const float s4  = s01 + (v.z + v.w);
                float4 o;
                o.x = run + v.x;
                o.y = run + s01;
                o.z = o.y + v.z;
                o.w = run + s4;
                rr[q] = o;
                run   = o.w;
            }
        }
        __syncthreads();

        // Gather: prefix-difference row sums (all lanes active, no decode).
        for (int n = tid; n < cnt; n += THREADS) {
            const uint32_t bnd = s_bnd[n];
            const int hs = bnd & 0xff;
            const int he = (bnd >> 8) & 0xff;
            const int ws = (bnd >> 16) & 0xff;
            const int we = bnd >> 24;

            const int area = (he - hs) * (we - ws);
            float val = 0.0f;
            if (area > 0) {
                float acc = 0.0f;
                const float* __restrict__ right = sp + (we - 1);
                if (ws > 0) {
                    const float* __restrict__ left = sp + (ws - 1);
                    for (int hy = hs; hy < he; ++hy)
                        acc += right[hy * WPF] - left[hy * WPF];
                } else {
                    for (int hy = hs; hy < he; ++hy)
                        acc += right[hy * WPF];
                }
                val = __fdiv_rn(acc, (float)area);
            }
            out[s_kk[n] * C_TOT + p] = val;
        }
        __syncthreads();   // gather done before next stage overwrites sp4
    }
}

extern "C" void kernel_launch(void* const* d_in, const int* in_sizes, int n_in,
                              void* d_out, int out_size)
{
    const float* x;
    const float* rois;
    if (n_in >= 2 && in_sizes[0] == KROIS * 5) {
        rois = (const float*)d_in[0];
        x    = (const float*)d_in[1];
    } else {
        x    = (const float*)d_in[0];
        rois = (const float*)d_in[1];
    }
    float* out = (float*)d_out;

    dim3 grid(PH * PW, C_OUT / CGRP, NBATCH);   // (49, 3, 4)
    psroi_fused7<<<grid, THREADS>>>(x, rois, out);
}